// round 1
// baseline (speedup 1.0000x reference)
#include <cuda_runtime.h>
#include <math.h>

// ---------------------------------------------------------------------------
// Scratch buffers (device globals — no allocation allowed)
// ---------------------------------------------------------------------------
__device__ float g_bwt [(size_t)4*512*128*128]; // 134 MB  bwt output / 1x1 result (+bwt, in place)
__device__ float g_r1  [(size_t)4*64*128*128];  // 16.8 MB relu(conv body1)
__device__ float g_r2  [(size_t)4*512*128*128]; // 134 MB  conv body2
__device__ float g_pool[(size_t)4*2*128*128];   // channel max/avg
__device__ float g_sal [(size_t)4*128*128];     // spatial attention map
__device__ float g_m   [4*512];                 // weighted channel means
__device__ float g_cal [4*512];                 // channel attention vector
__device__ float g_wave[(size_t)4*64*256*256];  // 67 MB   ibwt output

// ---------------------------------------------------------------------------
// K1: BWT  x(4,64,256,256) -> (4,512,128,128)
// ---------------------------------------------------------------------------
__global__ void bwt_kernel(const float* __restrict__ x, float* __restrict__ o)
{
    int idx = blockIdx.x * 256 + threadIdx.x;   // 4*64*128*128 threads
    int j = idx & 127;
    int i = (idx >> 7) & 127;
    int c = (idx >> 14) & 63;
    int b = idx >> 20;
    const float* xp = x + ((size_t)(b*64 + c)*256 + 2*i)*256 + 2*j;
    float2 r0 = *(const float2*)xp;          // even row: (even col, odd col)
    float2 r1 = *(const float2*)(xp + 256);  // odd row
    float x1 = r0.x*0.5f, x3 = r0.y*0.5f, x2 = r1.x*0.5f, x4 = r1.y*0.5f;
    size_t ob = ((size_t)(b*512 + c) << 14) + (i << 7) + j;
    const size_t gs = (size_t)64 << 14;
    o[ob + 0*gs] =  x1 + x2 + x3 + x4;   // LL
    o[ob + 1*gs] = -x1 - x2 + x3 + x4;   // HL
    o[ob + 2*gs] = -x1 + x2 - x3 + x4;   // LH
    o[ob + 3*gs] =  x1 - x2 - x3 + x4;   // HH
    o[ob + 4*gs] =  x1 + x2 - x3 - x4;   // HD
    o[ob + 5*gs] = -x1 + x2 + x3 - x4;   // LV
    o[ob + 6*gs] =  x1 - x2 + x3 - x4;   // LD
    o[ob + 7*gs] = -x1 - x2 - x3 - x4;   // HV
}

// ---------------------------------------------------------------------------
// Tiled direct 3x3 conv (pad=1). 32x32 spatial tile, 16 output channels per
// block, 8-input-channel chunks in smem, 2x2 register blocking per thread.
// ---------------------------------------------------------------------------
template<int CIN, int COUT, int HH, bool RELU, bool ADD_OUT>
__global__ __launch_bounds__(256, 2)
void conv3x3_kernel(const float* __restrict__ in, const float* __restrict__ w,
                    float* out)
{
    constexpr int CCH = 8;     // input channels per chunk
    constexpr int COB = 16;    // output channels per block
    __shared__ float sIn[CCH][34][34];
    __shared__ float sW[CCH][9][COB];

    const int t  = threadIdx.x;
    const int qx = t & 15, qy = t >> 4;
    const int tx = qx * 2, ty = qy * 2;
    const int z   = blockIdx.z;
    const int coT = z % (COUT / COB);
    const int b   = z / (COUT / COB);
    const int bx0 = blockIdx.x * 32, by0 = blockIdx.y * 32;

    float acc[COB][4];
    #pragma unroll
    for (int i = 0; i < COB; ++i) { acc[i][0]=acc[i][1]=acc[i][2]=acc[i][3]=0.f; }

    for (int cc = 0; cc < CIN / CCH; ++cc) {
        const int cb = cc * CCH;
        // stage input halo tile
        for (int idx = t; idx < CCH*34*34; idx += 256) {
            int ci = idx / 1156;
            int r  = idx - ci*1156;
            int y  = r / 34;
            int x  = r - y*34;
            int gy = by0 - 1 + y;
            int gx = bx0 - 1 + x;
            float v = 0.f;
            if (gy >= 0 && gy < HH && gx >= 0 && gx < HH)
                v = in[((size_t)(b*CIN + cb + ci)*HH + gy)*HH + gx];
            sIn[ci][y][x] = v;
        }
        // stage weights [ci][tap][co]
        for (int idx = t; idx < COB*CCH*9; idx += 256) {
            int co = idx / 72;
            int r  = idx - co*72;
            int ci = r / 9;
            int k  = r - ci*9;
            sW[ci][k][co] = w[((size_t)(coT*COB + co)*CIN + cb + ci)*9 + k];
        }
        __syncthreads();

        for (int ci = 0; ci < CCH; ++ci) {
            float patch[4][4];
            #pragma unroll
            for (int r = 0; r < 4; ++r)
                #pragma unroll
                for (int c2 = 0; c2 < 4; ++c2)
                    patch[r][c2] = sIn[ci][ty + r][tx + c2];
            #pragma unroll
            for (int k = 0; k < 9; ++k) {
                const int ky = k / 3, kx = k % 3;
                #pragma unroll
                for (int co = 0; co < COB; ++co) {
                    float wv = sW[ci][k][co];
                    acc[co][0] += patch[ky  ][kx  ] * wv;
                    acc[co][1] += patch[ky  ][kx+1] * wv;
                    acc[co][2] += patch[ky+1][kx  ] * wv;
                    acc[co][3] += patch[ky+1][kx+1] * wv;
                }
            }
        }
        __syncthreads();
    }

    const int oy = by0 + ty, ox = bx0 + tx;
    #pragma unroll
    for (int co = 0; co < COB; ++co) {
        size_t o0 = ((size_t)(b*COUT + coT*COB + co)*HH + oy)*HH + ox;
        #pragma unroll
        for (int q = 0; q < 4; ++q) {
            float r = acc[co][q];
            if (RELU) r = fmaxf(r, 0.f);
            size_t oi = o0 + (size_t)(q >> 1)*HH + (q & 1);
            if (ADD_OUT) r += out[oi];
            out[oi] = r;
        }
    }
}

// ---------------------------------------------------------------------------
// 1x1 conv as GEMM: 64 cout x 128 pixels per block. Optional fusions:
//   SALCAL : weight *= cal[ci] (channel attn), output *= sal[pixel] (spatial attn)
//   ADD_IN : out += existing out content (used for "+ x_bwt" in place)
// ---------------------------------------------------------------------------
template<int COUT, int CIN, int HW, bool SALCAL, bool ADD_IN>
__global__ __launch_bounds__(256)
void conv1x1_kernel(const float* __restrict__ in, const float* __restrict__ w,
                    const float* __restrict__ sal, const float* __restrict__ cal,
                    float* out)
{
    __shared__ __align__(16) float sIn[16][128];
    __shared__ __align__(16) float sW [16][64];
    const int t  = threadIdx.x;
    const int tp = t & 31, tc = t >> 5;
    const int p0 = tp * 4, co0 = tc * 8;
    const int pBase  = blockIdx.x * 128;
    const int b      = blockIdx.y;
    const int coBase = blockIdx.z * 64;

    float acc[8][4];
    #pragma unroll
    for (int i = 0; i < 8; ++i) { acc[i][0]=acc[i][1]=acc[i][2]=acc[i][3]=0.f; }

    for (int kc = 0; kc < CIN / 16; ++kc) {
        const int kBase = kc * 16;
        #pragma unroll
        for (int i = t; i < 512; i += 256) {          // 16 x 128 floats as float4
            int k = i >> 5, x4 = i & 31;
            float4 v = *(const float4*)(in + (size_t)(b*CIN + kBase + k)*HW + pBase + x4*4);
            *(float4*)&sIn[k][x4*4] = v;
        }
        #pragma unroll
        for (int i = t; i < 1024; i += 256) {         // 16 x 64 weights
            int co = i >> 4, k = i & 15;
            float v = w[(size_t)(coBase + co)*CIN + kBase + k];
            if (SALCAL) v *= cal[b*CIN + kBase + k];
            sW[k][co] = v;
        }
        __syncthreads();
        #pragma unroll
        for (int k = 0; k < 16; ++k) {
            float4 v  = *(const float4*)&sIn[k][p0];
            float4 wl = *(const float4*)&sW[k][co0];
            float4 wh = *(const float4*)&sW[k][co0 + 4];
            float va[4] = {v.x, v.y, v.z, v.w};
            float wa[8] = {wl.x, wl.y, wl.z, wl.w, wh.x, wh.y, wh.z, wh.w};
            #pragma unroll
            for (int co = 0; co < 8; ++co)
                #pragma unroll
                for (int j = 0; j < 4; ++j)
                    acc[co][j] += wa[co] * va[j];
        }
        __syncthreads();
    }

    const int pg = pBase + p0;
    float4 sv = make_float4(1.f, 1.f, 1.f, 1.f);
    if (SALCAL) sv = *(const float4*)(sal + ((size_t)b)*HW + pg);
    #pragma unroll
    for (int co = 0; co < 8; ++co) {
        size_t oi = (size_t)(b*COUT + coBase + co0 + co)*HW + pg;
        float4 r = make_float4(acc[co][0]*sv.x, acc[co][1]*sv.y,
                               acc[co][2]*sv.z, acc[co][3]*sv.w);
        if (ADD_IN) {
            float4 pv = *(const float4*)(out + oi);
            r.x += pv.x; r.y += pv.y; r.z += pv.z; r.w += pv.w;
        }
        *(float4*)(out + oi) = r;
    }
}

// ---------------------------------------------------------------------------
// K4: channel max/mean pooling over 512 channels at each pixel
// ---------------------------------------------------------------------------
__global__ void chanpool_kernel(const float* __restrict__ r2, float* __restrict__ pool)
{
    int p = blockIdx.x * 256 + threadIdx.x;
    int b = blockIdx.y;
    const float* base = r2 + (((size_t)b*512) << 14) + p;
    float mx = -3.4e38f, s = 0.f;
    #pragma unroll 8
    for (int c = 0; c < 512; ++c) {
        float v = base[(size_t)c << 14];
        mx = fmaxf(mx, v);
        s += v;
    }
    pool[(((size_t)(b*2    )) << 14) + p] = mx;
    pool[(((size_t)(b*2 + 1)) << 14) + p] = s * (1.f/512.f);
}

// ---------------------------------------------------------------------------
// K5: 5x5 conv (2->1, pad 2) + sigmoid -> spatial attention map
// ---------------------------------------------------------------------------
__global__ void salconv_kernel(const float* __restrict__ pool,
                               const float* __restrict__ wsal,
                               float* __restrict__ sal)
{
    int p = blockIdx.x * 256 + threadIdx.x;
    int b = blockIdx.y;
    int y = p >> 7, x = p & 127;
    float a = 0.f;
    #pragma unroll
    for (int c = 0; c < 2; ++c) {
        const float* pp = pool + (((size_t)(b*2 + c)) << 14);
        #pragma unroll
        for (int ky = 0; ky < 5; ++ky) {
            int iy = y + ky - 2;
            if (iy < 0 || iy >= 128) continue;
            #pragma unroll
            for (int kx = 0; kx < 5; ++kx) {
                int ix = x + kx - 2;
                if (ix < 0 || ix >= 128) continue;
                a += wsal[c*25 + ky*5 + kx] * pp[(iy << 7) + ix];
            }
        }
    }
    sal[(((size_t)b) << 14) + p] = 1.f / (1.f + expf(-a));
}

// ---------------------------------------------------------------------------
// K6: weighted channel mean  m[b,c] = mean_p( r2[b,c,p] * sal[b,p] )
// ---------------------------------------------------------------------------
__global__ void wmean_kernel(const float* __restrict__ r2,
                             const float* __restrict__ sal,
                             float* __restrict__ m)
{
    int c = blockIdx.x, b = blockIdx.y;
    const float* r = r2 + (((size_t)(b*512 + c)) << 14);
    const float* s = sal + (((size_t)b) << 14);
    float sum = 0.f;
    for (int i = threadIdx.x; i < 16384; i += 256) sum += r[i] * s[i];
    #pragma unroll
    for (int o = 16; o > 0; o >>= 1) sum += __shfl_xor_sync(0xffffffffu, sum, o);
    __shared__ float red[8];
    if ((threadIdx.x & 31) == 0) red[threadIdx.x >> 5] = sum;
    __syncthreads();
    if (threadIdx.x == 0) {
        float tot = 0.f;
        #pragma unroll
        for (int i = 0; i < 8; ++i) tot += red[i];
        m[b*512 + c] = tot * (1.f/16384.f);
    }
}

// ---------------------------------------------------------------------------
// K7: channel-attention MLP: cal = sigmoid(W2 * relu(W1 * m))
// ---------------------------------------------------------------------------
__global__ void calmlp_kernel(const float* __restrict__ m,
                              const float* __restrict__ wca1,
                              const float* __restrict__ wca2,
                              float* __restrict__ cal)
{
    int b = blockIdx.x;
    __shared__ float sm[512];
    __shared__ float sy1[32];
    for (int i = threadIdx.x; i < 512; i += 256) sm[i] = m[b*512 + i];
    __syncthreads();
    if (threadIdx.x < 32) {
        float a = 0.f;
        for (int c = 0; c < 512; ++c) a += wca1[threadIdx.x*512 + c] * sm[c];
        sy1[threadIdx.x] = fmaxf(a, 0.f);
    }
    __syncthreads();
    for (int c = threadIdx.x; c < 512; c += 256) {
        float a = 0.f;
        #pragma unroll
        for (int j = 0; j < 32; ++j) a += wca2[c*32 + j] * sy1[j];
        cal[b*512 + c] = 1.f / (1.f + expf(-a));
    }
}

// ---------------------------------------------------------------------------
// K9: IBWT  (4,512,128,128) -> (4,64,256,256)
// ---------------------------------------------------------------------------
__global__ void ibwt_kernel(const float* __restrict__ r, float* __restrict__ o)
{
    int idx = blockIdx.x * 256 + threadIdx.x;
    int j = idx & 127;
    int i = (idx >> 7) & 127;
    int c = (idx >> 14) & 63;
    int b = idx >> 20;
    size_t base = ((size_t)(b*512 + c) << 14) + (i << 7) + j;
    const size_t gs = (size_t)64 << 14;
    float x1 = r[base       ]*0.5f, x2 = r[base +   gs]*0.5f;
    float x3 = r[base + 2*gs]*0.5f, x4 = r[base + 3*gs]*0.5f;
    float x5 = r[base + 4*gs]*0.5f, x6 = r[base + 5*gs]*0.5f;
    float x7 = r[base + 6*gs]*0.5f, x8 = r[base + 7*gs]*0.5f;
    float a00 = x1 - x2 - x3 + x4 + x5 - x6 + x7 - x8;
    float a10 = x1 - x2 + x3 - x4 - x5 + x6 - x7 + x8;
    float a01 = x1 + x2 - x3 - x4 - x5 - x6 + x7 + x8;
    float a11 = x1 + x2 + x3 + x4 + x5 + x6 + x7 + x8;
    float* op = o + ((size_t)(b*64 + c)*256 + 2*i)*256 + 2*j;
    *(float2*)op         = make_float2(a00, a01);
    *(float2*)(op + 256) = make_float2(a10, a11);
}

// ---------------------------------------------------------------------------
// Launch
// ---------------------------------------------------------------------------
extern "C" void kernel_launch(void* const* d_in, const int* in_sizes, int n_in,
                              void* d_out, int out_size)
{
    const float* x       = (const float*)d_in[0];
    const float* w_body1 = (const float*)d_in[1];
    const float* w_body2 = (const float*)d_in[2];
    const float* w_sal   = (const float*)d_in[3];
    const float* w_ca1   = (const float*)d_in[4];
    const float* w_ca2   = (const float*)d_in[5];
    const float* w_1x1   = (const float*)d_in[6];
    const float* w_3x3   = (const float*)d_in[7];
    const float* w_final = (const float*)d_in[8];
    float* out = (float*)d_out;

    float *bwt, *r1, *r2, *pool, *sal, *m, *cal, *wave;
    cudaGetSymbolAddress((void**)&bwt,  g_bwt);
    cudaGetSymbolAddress((void**)&r1,   g_r1);
    cudaGetSymbolAddress((void**)&r2,   g_r2);
    cudaGetSymbolAddress((void**)&pool, g_pool);
    cudaGetSymbolAddress((void**)&sal,  g_sal);
    cudaGetSymbolAddress((void**)&m,    g_m);
    cudaGetSymbolAddress((void**)&cal,  g_cal);
    cudaGetSymbolAddress((void**)&wave, g_wave);

    // 1) BWT
    bwt_kernel<<<16384, 256>>>(x, bwt);
    // 2) conv body1 3x3 (512 -> 64) + relu
    conv3x3_kernel<512, 64, 128, true, false><<<dim3(4,4,16), 256>>>(bwt, w_body1, r1);
    // 3) conv body2 3x3 (64 -> 512)
    conv3x3_kernel<64, 512, 128, false, false><<<dim3(4,4,128), 256>>>(r1, w_body2, r2);
    // 4) channel pooling (max/avg)
    chanpool_kernel<<<dim3(64,4), 256>>>(r2, pool);
    // 5) 5x5 conv + sigmoid -> sal map
    salconv_kernel<<<dim3(64,4), 256>>>(pool, w_sal, sal);
    // 6) weighted channel means (cal path sees sal(res))
    wmean_kernel<<<dim3(512,4), 256>>>(r2, sal, m);
    // 7) channel attention MLP
    calmlp_kernel<<<4, 256>>>(m, w_ca1, w_ca2, cal);
    // 8) 1x1 conv (512->512) with cal folded into weights, sal in epilogue,
    //    "+ x_bwt" applied in place on the bwt buffer
    conv1x1_kernel<512, 512, 16384, true, true><<<dim3(128,4,8), 256>>>(r2, w_1x1, sal, cal, bwt);
    // 9) IBWT
    ibwt_kernel<<<16384, 256>>>(bwt, wave);
    // 10) final 1x1 conv of residual -> out
    conv1x1_kernel<64, 64, 65536, false, false><<<dim3(512,4,1), 256>>>(x, w_final, nullptr, nullptr, out);
    // 11) final 3x3 conv + relu, added onto out
    conv3x3_kernel<64, 64, 256, true, true><<<dim3(8,8,16), 256>>>(wave, w_3x3, out);
}

// round 2
// speedup vs baseline: 1.0020x; 1.0020x over previous
#include <cuda_runtime.h>
#include <math.h>

// ---------------------------------------------------------------------------
// Scratch buffers (device globals — no allocation allowed)
// ---------------------------------------------------------------------------
__device__ float g_bwt [(size_t)4*512*128*128]; // 134 MB  bwt output / 1x1 result (+bwt, in place)
__device__ float g_r1  [(size_t)4*64*128*128];  // 16.8 MB relu(conv body1)
__device__ float g_r2  [(size_t)4*512*128*128]; // 134 MB  conv body2
__device__ float g_pool[(size_t)4*2*128*128];   // channel max/avg
__device__ float g_sal [(size_t)4*128*128];     // spatial attention map
__device__ float g_m   [4*512];                 // weighted channel means
__device__ float g_cal [4*512];                 // channel attention vector
__device__ float g_wave[(size_t)4*64*256*256];  // 67 MB   ibwt output

// ---------------------------------------------------------------------------
// K1: BWT  x(4,64,256,256) -> (4,512,128,128)
// ---------------------------------------------------------------------------
__global__ void bwt_kernel(const float* __restrict__ x, float* __restrict__ o)
{
    int idx = blockIdx.x * 256 + threadIdx.x;   // 4*64*128*128 threads
    int j = idx & 127;
    int i = (idx >> 7) & 127;
    int c = (idx >> 14) & 63;
    int b = idx >> 20;
    const float* xp = x + ((size_t)(b*64 + c)*256 + 2*i)*256 + 2*j;
    float2 r0 = *(const float2*)xp;          // even row: (even col, odd col)
    float2 r1 = *(const float2*)(xp + 256);  // odd row
    float x1 = r0.x*0.5f, x3 = r0.y*0.5f, x2 = r1.x*0.5f, x4 = r1.y*0.5f;
    size_t ob = ((size_t)(b*512 + c) << 14) + (i << 7) + j;
    const size_t gs = (size_t)64 << 14;
    o[ob + 0*gs] =  x1 + x2 + x3 + x4;   // LL
    o[ob + 1*gs] = -x1 - x2 + x3 + x4;   // HL
    o[ob + 2*gs] = -x1 + x2 - x3 + x4;   // LH
    o[ob + 3*gs] =  x1 - x2 - x3 + x4;   // HH
    o[ob + 4*gs] =  x1 + x2 - x3 - x4;   // HD
    o[ob + 5*gs] = -x1 + x2 + x3 - x4;   // LV
    o[ob + 6*gs] =  x1 - x2 + x3 - x4;   // LD
    o[ob + 7*gs] = -x1 - x2 - x3 - x4;   // HV
}

// ---------------------------------------------------------------------------
// Tiled direct 3x3 conv (pad=1). 32x32 spatial tile, 16 output channels per
// block, 8-input-channel chunks in smem, 2x2 register blocking per thread.
// ---------------------------------------------------------------------------
template<int CIN, int COUT, int HH, bool RELU, bool ADD_OUT>
__global__ __launch_bounds__(256, 2)
void conv3x3_kernel(const float* __restrict__ in, const float* __restrict__ w,
                    float* out)
{
    constexpr int CCH = 8;     // input channels per chunk
    constexpr int COB = 16;    // output channels per block
    __shared__ float sIn[CCH][34][34];
    __shared__ float sW[CCH][9][COB];

    const int t  = threadIdx.x;
    const int qx = t & 15, qy = t >> 4;
    const int tx = qx * 2, ty = qy * 2;
    const int z   = blockIdx.z;
    const int coT = z % (COUT / COB);
    const int b   = z / (COUT / COB);
    const int bx0 = blockIdx.x * 32, by0 = blockIdx.y * 32;

    float acc[COB][4];
    #pragma unroll
    for (int i = 0; i < COB; ++i) { acc[i][0]=acc[i][1]=acc[i][2]=acc[i][3]=0.f; }

    for (int cc = 0; cc < CIN / CCH; ++cc) {
        const int cb = cc * CCH;
        // stage input halo tile
        for (int idx = t; idx < CCH*34*34; idx += 256) {
            int ci = idx / 1156;
            int r  = idx - ci*1156;
            int y  = r / 34;
            int x  = r - y*34;
            int gy = by0 - 1 + y;
            int gx = bx0 - 1 + x;
            float v = 0.f;
            if (gy >= 0 && gy < HH && gx >= 0 && gx < HH)
                v = in[((size_t)(b*CIN + cb + ci)*HH + gy)*HH + gx];
            sIn[ci][y][x] = v;
        }
        // stage weights [ci][tap][co]
        for (int idx = t; idx < COB*CCH*9; idx += 256) {
            int co = idx / 72;
            int r  = idx - co*72;
            int ci = r / 9;
            int k  = r - ci*9;
            sW[ci][k][co] = w[((size_t)(coT*COB + co)*CIN + cb + ci)*9 + k];
        }
        __syncthreads();

        for (int ci = 0; ci < CCH; ++ci) {
            float patch[4][4];
            #pragma unroll
            for (int r = 0; r < 4; ++r)
                #pragma unroll
                for (int c2 = 0; c2 < 4; ++c2)
                    patch[r][c2] = sIn[ci][ty + r][tx + c2];
            #pragma unroll
            for (int k = 0; k < 9; ++k) {
                const int ky = k / 3, kx = k % 3;
                #pragma unroll
                for (int co = 0; co < COB; ++co) {
                    float wv = sW[ci][k][co];
                    acc[co][0] += patch[ky  ][kx  ] * wv;
                    acc[co][1] += patch[ky  ][kx+1] * wv;
                    acc[co][2] += patch[ky+1][kx  ] * wv;
                    acc[co][3] += patch[ky+1][kx+1] * wv;
                }
            }
        }
        __syncthreads();
    }

    const int oy = by0 + ty, ox = bx0 + tx;
    #pragma unroll
    for (int co = 0; co < COB; ++co) {
        size_t o0 = ((size_t)(b*COUT + coT*COB + co)*HH + oy)*HH + ox;
        #pragma unroll
        for (int q = 0; q < 4; ++q) {
            float r = acc[co][q];
            if (RELU) r = fmaxf(r, 0.f);
            size_t oi = o0 + (size_t)(q >> 1)*HH + (q & 1);
            if (ADD_OUT) r += out[oi];
            out[oi] = r;
        }
    }
}

// ---------------------------------------------------------------------------
// 1x1 conv as GEMM: 64 cout x 128 pixels per block. Optional fusions:
//   SALCAL : weight *= cal[ci] (channel attn), output *= sal[pixel] (spatial attn)
//   ADD_IN : out += existing out content (used for "+ x_bwt" in place)
// ---------------------------------------------------------------------------
template<int COUT, int CIN, int HW, bool SALCAL, bool ADD_IN>
__global__ __launch_bounds__(256)
void conv1x1_kernel(const float* __restrict__ in, const float* __restrict__ w,
                    const float* __restrict__ sal, const float* __restrict__ cal,
                    float* out)
{
    __shared__ __align__(16) float sIn[16][128];
    __shared__ __align__(16) float sW [16][64];
    const int t  = threadIdx.x;
    const int tp = t & 31, tc = t >> 5;
    const int p0 = tp * 4, co0 = tc * 8;
    const int pBase  = blockIdx.x * 128;
    const int b      = blockIdx.y;
    const int coBase = blockIdx.z * 64;

    float acc[8][4];
    #pragma unroll
    for (int i = 0; i < 8; ++i) { acc[i][0]=acc[i][1]=acc[i][2]=acc[i][3]=0.f; }

    for (int kc = 0; kc < CIN / 16; ++kc) {
        const int kBase = kc * 16;
        #pragma unroll
        for (int i = t; i < 512; i += 256) {          // 16 x 128 floats as float4
            int k = i >> 5, x4 = i & 31;
            float4 v = *(const float4*)(in + (size_t)(b*CIN + kBase + k)*HW + pBase + x4*4);
            *(float4*)&sIn[k][x4*4] = v;
        }
        #pragma unroll
        for (int i = t; i < 1024; i += 256) {         // 16 x 64 weights
            int co = i >> 4, k = i & 15;
            float v = w[(size_t)(coBase + co)*CIN + kBase + k];
            if (SALCAL) v *= cal[b*CIN + kBase + k];
            sW[k][co] = v;
        }
        __syncthreads();
        #pragma unroll
        for (int k = 0; k < 16; ++k) {
            float4 v  = *(const float4*)&sIn[k][p0];
            float4 wl = *(const float4*)&sW[k][co0];
            float4 wh = *(const float4*)&sW[k][co0 + 4];
            float va[4] = {v.x, v.y, v.z, v.w};
            float wa[8] = {wl.x, wl.y, wl.z, wl.w, wh.x, wh.y, wh.z, wh.w};
            #pragma unroll
            for (int co = 0; co < 8; ++co)
                #pragma unroll
                for (int j = 0; j < 4; ++j)
                    acc[co][j] += wa[co] * va[j];
        }
        __syncthreads();
    }

    const int pg = pBase + p0;
    float4 sv = make_float4(1.f, 1.f, 1.f, 1.f);
    if (SALCAL) sv = *(const float4*)(sal + ((size_t)b)*HW + pg);
    #pragma unroll
    for (int co = 0; co < 8; ++co) {
        size_t oi = (size_t)(b*COUT + coBase + co0 + co)*HW + pg;
        float4 r = make_float4(acc[co][0]*sv.x, acc[co][1]*sv.y,
                               acc[co][2]*sv.z, acc[co][3]*sv.w);
        if (ADD_IN) {
            float4 pv = *(const float4*)(out + oi);
            r.x += pv.x; r.y += pv.y; r.z += pv.z; r.w += pv.w;
        }
        *(float4*)(out + oi) = r;
    }
}

// ---------------------------------------------------------------------------
// K4: channel max/mean pooling over 512 channels at each pixel
// ---------------------------------------------------------------------------
__global__ void chanpool_kernel(const float* __restrict__ r2, float* __restrict__ pool)
{
    int p = blockIdx.x * 256 + threadIdx.x;
    int b = blockIdx.y;
    const float* base = r2 + (((size_t)b*512) << 14) + p;
    float mx = -3.4e38f, s = 0.f;
    #pragma unroll 8
    for (int c = 0; c < 512; ++c) {
        float v = base[(size_t)c << 14];
        mx = fmaxf(mx, v);
        s += v;
    }
    pool[(((size_t)(b*2    )) << 14) + p] = mx;
    pool[(((size_t)(b*2 + 1)) << 14) + p] = s * (1.f/512.f);
}

// ---------------------------------------------------------------------------
// K5: 5x5 conv (2->1, pad 2) + sigmoid -> spatial attention map
// ---------------------------------------------------------------------------
__global__ void salconv_kernel(const float* __restrict__ pool,
                               const float* __restrict__ wsal,
                               float* __restrict__ sal)
{
    int p = blockIdx.x * 256 + threadIdx.x;
    int b = blockIdx.y;
    int y = p >> 7, x = p & 127;
    float a = 0.f;
    #pragma unroll
    for (int c = 0; c < 2; ++c) {
        const float* pp = pool + (((size_t)(b*2 + c)) << 14);
        #pragma unroll
        for (int ky = 0; ky < 5; ++ky) {
            int iy = y + ky - 2;
            if (iy < 0 || iy >= 128) continue;
            #pragma unroll
            for (int kx = 0; kx < 5; ++kx) {
                int ix = x + kx - 2;
                if (ix < 0 || ix >= 128) continue;
                a += wsal[c*25 + ky*5 + kx] * pp[(iy << 7) + ix];
            }
        }
    }
    sal[(((size_t)b) << 14) + p] = 1.f / (1.f + expf(-a));
}

// ---------------------------------------------------------------------------
// K6: weighted channel mean  m[b,c] = mean_p( r2[b,c,p] * sal[b,p] )
// ---------------------------------------------------------------------------
__global__ void wmean_kernel(const float* __restrict__ r2,
                             const float* __restrict__ sal,
                             float* __restrict__ m)
{
    int c = blockIdx.x, b = blockIdx.y;
    const float* r = r2 + (((size_t)(b*512 + c)) << 14);
    const float* s = sal + (((size_t)b) << 14);
    float sum = 0.f;
    for (int i = threadIdx.x; i < 16384; i += 256) sum += r[i] * s[i];
    #pragma unroll
    for (int o = 16; o > 0; o >>= 1) sum += __shfl_xor_sync(0xffffffffu, sum, o);
    __shared__ float red[8];
    if ((threadIdx.x & 31) == 0) red[threadIdx.x >> 5] = sum;
    __syncthreads();
    if (threadIdx.x == 0) {
        float tot = 0.f;
        #pragma unroll
        for (int i = 0; i < 8; ++i) tot += red[i];
        m[b*512 + c] = tot * (1.f/16384.f);
    }
}

// ---------------------------------------------------------------------------
// K7: channel-attention MLP: cal = sigmoid(W2 * relu(W1 * m))
// ---------------------------------------------------------------------------
__global__ void calmlp_kernel(const float* __restrict__ m,
                              const float* __restrict__ wca1,
                              const float* __restrict__ wca2,
                              float* __restrict__ cal)
{
    int b = blockIdx.x;
    __shared__ float sm[512];
    __shared__ float sy1[32];
    for (int i = threadIdx.x; i < 512; i += 256) sm[i] = m[b*512 + i];
    __syncthreads();
    if (threadIdx.x < 32) {
        float a = 0.f;
        for (int c = 0; c < 512; ++c) a += wca1[threadIdx.x*512 + c] * sm[c];
        sy1[threadIdx.x] = fmaxf(a, 0.f);
    }
    __syncthreads();
    for (int c = threadIdx.x; c < 512; c += 256) {
        float a = 0.f;
        #pragma unroll
        for (int j = 0; j < 32; ++j) a += wca2[c*32 + j] * sy1[j];
        cal[b*512 + c] = 1.f / (1.f + expf(-a));
    }
}

// ---------------------------------------------------------------------------
// K9: IBWT  (4,512,128,128) -> (4,64,256,256)
// ---------------------------------------------------------------------------
__global__ void ibwt_kernel(const float* __restrict__ r, float* __restrict__ o)
{
    int idx = blockIdx.x * 256 + threadIdx.x;
    int j = idx & 127;
    int i = (idx >> 7) & 127;
    int c = (idx >> 14) & 63;
    int b = idx >> 20;
    size_t base = ((size_t)(b*512 + c) << 14) + (i << 7) + j;
    const size_t gs = (size_t)64 << 14;
    float x1 = r[base       ]*0.5f, x2 = r[base +   gs]*0.5f;
    float x3 = r[base + 2*gs]*0.5f, x4 = r[base + 3*gs]*0.5f;
    float x5 = r[base + 4*gs]*0.5f, x6 = r[base + 5*gs]*0.5f;
    float x7 = r[base + 6*gs]*0.5f, x8 = r[base + 7*gs]*0.5f;
    float a00 = x1 - x2 - x3 + x4 + x5 - x6 + x7 - x8;
    float a10 = x1 - x2 + x3 - x4 - x5 + x6 - x7 + x8;
    float a01 = x1 + x2 - x3 - x4 - x5 - x6 + x7 + x8;
    float a11 = x1 + x2 + x3 + x4 + x5 + x6 + x7 + x8;
    float* op = o + ((size_t)(b*64 + c)*256 + 2*i)*256 + 2*j;
    *(float2*)op         = make_float2(a00, a01);
    *(float2*)(op + 256) = make_float2(a10, a11);
}

// ---------------------------------------------------------------------------
// Launch
// ---------------------------------------------------------------------------
extern "C" void kernel_launch(void* const* d_in, const int* in_sizes, int n_in,
                              void* d_out, int out_size)
{
    const float* x       = (const float*)d_in[0];
    const float* w_body1 = (const float*)d_in[1];
    const float* w_body2 = (const float*)d_in[2];
    const float* w_sal   = (const float*)d_in[3];
    const float* w_ca1   = (const float*)d_in[4];
    const float* w_ca2   = (const float*)d_in[5];
    const float* w_1x1   = (const float*)d_in[6];
    const float* w_3x3   = (const float*)d_in[7];
    const float* w_final = (const float*)d_in[8];
    float* out = (float*)d_out;

    float *bwt, *r1, *r2, *pool, *sal, *m, *cal, *wave;
    cudaGetSymbolAddress((void**)&bwt,  g_bwt);
    cudaGetSymbolAddress((void**)&r1,   g_r1);
    cudaGetSymbolAddress((void**)&r2,   g_r2);
    cudaGetSymbolAddress((void**)&pool, g_pool);
    cudaGetSymbolAddress((void**)&sal,  g_sal);
    cudaGetSymbolAddress((void**)&m,    g_m);
    cudaGetSymbolAddress((void**)&cal,  g_cal);
    cudaGetSymbolAddress((void**)&wave, g_wave);

    // 1) BWT
    bwt_kernel<<<16384, 256>>>(x, bwt);
    // 2) conv body1 3x3 (512 -> 64) + relu
    conv3x3_kernel<512, 64, 128, true, false><<<dim3(4,4,16), 256>>>(bwt, w_body1, r1);
    // 3) conv body2 3x3 (64 -> 512)
    conv3x3_kernel<64, 512, 128, false, false><<<dim3(4,4,128), 256>>>(r1, w_body2, r2);
    // 4) channel pooling (max/avg)
    chanpool_kernel<<<dim3(64,4), 256>>>(r2, pool);
    // 5) 5x5 conv + sigmoid -> sal map
    salconv_kernel<<<dim3(64,4), 256>>>(pool, w_sal, sal);
    // 6) weighted channel means (cal path sees sal(res))
    wmean_kernel<<<dim3(512,4), 256>>>(r2, sal, m);
    // 7) channel attention MLP
    calmlp_kernel<<<4, 256>>>(m, w_ca1, w_ca2, cal);
    // 8) 1x1 conv (512->512) with cal folded into weights, sal in epilogue,
    //    "+ x_bwt" applied in place on the bwt buffer
    conv1x1_kernel<512, 512, 16384, true, true><<<dim3(128,4,8), 256>>>(r2, w_1x1, sal, cal, bwt);
    // 9) IBWT
    ibwt_kernel<<<16384, 256>>>(bwt, wave);
    // 10) final 1x1 conv of residual -> out
    conv1x1_kernel<64, 64, 65536, false, false><<<dim3(512,4,1), 256>>>(x, w_final, nullptr, nullptr, out);
    // 11) final 3x3 conv + relu, added onto out
    conv3x3_kernel<64, 64, 256, true, true><<<dim3(8,8,16), 256>>>(wave, w_3x3, out);
}